// round 1
// baseline (speedup 1.0000x reference)
#include <cuda_runtime.h>
#include <math.h>

// PINN forward + forward-mode JVPs (T, dT/dz, dT/dt, d2T/dz2)
// MLP: 3 -> 128 -> 128 -> 64 -> 1, tanh activations.
//
// Strategy: 32 points per block, 512 threads. For each point we propagate 4
// quantities (value, z-tangent, t-tangent, 2nd z-tangent) through the net.
// Each linear layer is a small register-tiled GEMM (same W for all 4
// quantities); tanh coupling rules are applied in the register epilogue.
// Activations live in shared memory laid out [quant][unit][point] so that
// lane index == point gives conflict-free LDS/STS. Weights are read via
// warp-uniform __ldg (L1-resident, ~100KB total).

#define TPB 512
#define PTS 32           // points per block
#define H1  128
#define H2  128
#define H3  64

// buffer: [4][128][32] floats = 16384 floats = 64KB
#define BUFQ (128 * 32)

__global__ __launch_bounds__(TPB, 1)
void pinn_fused_kernel(const float* __restrict__ x,
                       const float* __restrict__ W1, const float* __restrict__ b1,
                       const float* __restrict__ W2, const float* __restrict__ b2,
                       const float* __restrict__ W3, const float* __restrict__ b3,
                       const float* __restrict__ W4, const float* __restrict__ b4,
                       float* __restrict__ out)
{
    extern __shared__ float smem[];
    float* buf0 = smem;               // [4][128][32]
    float* buf1 = smem + 4 * BUFQ;    // [4][128][32]

    const int tid = threadIdx.x;
    const int p   = tid & 31;         // point within tile (lane id)
    const int blk = blockIdx.x;

    // ---------------- Layer 1: 3 -> 128 (direct, K=3) ----------------
    // input tangents: dz = (1,0,0), dt = (0,1,0), dzz = 0
    for (int idx = tid; idx < PTS * H1; idx += TPB) {
        int pp = idx & 31;
        int j  = idx >> 5;
        int pg = blk * PTS + pp;
        float x0 = x[pg * 3 + 0];
        float x1 = x[pg * 3 + 1];
        float x2 = x[pg * 3 + 2];
        float w0 = __ldg(&W1[j]);
        float w1 = __ldg(&W1[128 + j]);
        float w2 = __ldg(&W1[256 + j]);
        float u  = fmaf(x0, w0, fmaf(x1, w1, fmaf(x2, w2, __ldg(&b1[j]))));
        float h  = tanhf(u);
        float s  = 1.0f - h * h;
        float hdz  = s * w0;                 // s * u_dz, u_dz = W1[0][j]
        float hdt  = s * w1;                 // s * u_dt
        float hdzz = -2.0f * h * hdz * w0;   // s*0 - 2h*s*u_dz^2
        buf0[(0 * H1 + j) * 32 + pp] = h;
        buf0[(1 * H1 + j) * 32 + pp] = hdz;
        buf0[(2 * H1 + j) * 32 + pp] = hdt;
        buf0[(3 * H1 + j) * 32 + pp] = hdzz;
    }
    __syncthreads();

    // ---------------- Layer 2: 128 -> 128 ----------------
    // thread = (p = lane, jt = warp): 16 warps x 8 cols = 128 cols
    {
        const int jt = tid >> 5;       // 0..15
        const int j0 = jt * 8;
        float acc[4][8];
        #pragma unroll
        for (int c = 0; c < 8; c++) {
            acc[0][c] = __ldg(&b2[j0 + c]);
            acc[1][c] = 0.0f; acc[2][c] = 0.0f; acc[3][c] = 0.0f;
        }
        const float* a_base = buf0 + p;
        #pragma unroll 4
        for (int k = 0; k < H1; k++) {
            float a0 = a_base[(0 * H1 + k) * 32];
            float a1 = a_base[(1 * H1 + k) * 32];
            float a2 = a_base[(2 * H1 + k) * 32];
            float a3 = a_base[(3 * H1 + k) * 32];
            float4 wA = __ldg((const float4*)(W2 + k * H2 + j0));
            float4 wB = __ldg((const float4*)(W2 + k * H2 + j0 + 4));
            float w[8] = {wA.x, wA.y, wA.z, wA.w, wB.x, wB.y, wB.z, wB.w};
            #pragma unroll
            for (int c = 0; c < 8; c++) {
                acc[0][c] = fmaf(a0, w[c], acc[0][c]);
                acc[1][c] = fmaf(a1, w[c], acc[1][c]);
                acc[2][c] = fmaf(a2, w[c], acc[2][c]);
                acc[3][c] = fmaf(a3, w[c], acc[3][c]);
            }
        }
        #pragma unroll
        for (int c = 0; c < 8; c++) {
            int j = j0 + c;
            float h = tanhf(acc[0][c]);
            float s = 1.0f - h * h;
            float hdz  = s * acc[1][c];
            float hdt  = s * acc[2][c];
            float hdzz = fmaf(-2.0f * h * hdz, acc[1][c], s * acc[3][c]);
            buf1[(0 * H1 + j) * 32 + p] = h;
            buf1[(1 * H1 + j) * 32 + p] = hdz;
            buf1[(2 * H1 + j) * 32 + p] = hdt;
            buf1[(3 * H1 + j) * 32 + p] = hdzz;
        }
    }
    __syncthreads();

    // ---------------- Layer 3: 128 -> 64 ----------------
    // 16 warps x 4 cols = 64 cols. Output written compact: [4][64][32] in buf0.
    {
        const int jt = tid >> 5;       // 0..15
        const int j0 = jt * 4;
        float acc[4][4];
        #pragma unroll
        for (int c = 0; c < 4; c++) {
            acc[0][c] = __ldg(&b3[j0 + c]);
            acc[1][c] = 0.0f; acc[2][c] = 0.0f; acc[3][c] = 0.0f;
        }
        const float* a_base = buf1 + p;
        #pragma unroll 4
        for (int k = 0; k < H2; k++) {
            float a0 = a_base[(0 * H1 + k) * 32];
            float a1 = a_base[(1 * H1 + k) * 32];
            float a2 = a_base[(2 * H1 + k) * 32];
            float a3 = a_base[(3 * H1 + k) * 32];
            float4 wA = __ldg((const float4*)(W3 + k * H3 + j0));
            float w[4] = {wA.x, wA.y, wA.z, wA.w};
            #pragma unroll
            for (int c = 0; c < 4; c++) {
                acc[0][c] = fmaf(a0, w[c], acc[0][c]);
                acc[1][c] = fmaf(a1, w[c], acc[1][c]);
                acc[2][c] = fmaf(a2, w[c], acc[2][c]);
                acc[3][c] = fmaf(a3, w[c], acc[3][c]);
            }
        }
        #pragma unroll
        for (int c = 0; c < 4; c++) {
            int j = j0 + c;
            float h = tanhf(acc[0][c]);
            float s = 1.0f - h * h;
            float hdz  = s * acc[1][c];
            float hdt  = s * acc[2][c];
            float hdzz = fmaf(-2.0f * h * hdz, acc[1][c], s * acc[3][c]);
            buf0[(0 * H3 + j) * 32 + p] = h;
            buf0[(1 * H3 + j) * 32 + p] = hdz;
            buf0[(2 * H3 + j) * 32 + p] = hdt;
            buf0[(3 * H3 + j) * 32 + p] = hdzz;
        }
    }
    __syncthreads();

    // ---------------- Layer 4: 64 -> 1 (4 dots per point) ----------------
    if (tid < 128) {
        const int q = tid >> 5;        // quantity 0..3
        float dot = (q == 0) ? __ldg(&b4[0]) : 0.0f;
        const float* hb = buf0 + (q * H3) * 32 + p;
        #pragma unroll
        for (int k = 0; k < H3; k++)
            dot = fmaf(hb[k * 32], __ldg(&W4[k]), dot);
        out[(blk * PTS + p) * 4 + q] = dot;
    }
}

extern "C" void kernel_launch(void* const* d_in, const int* in_sizes, int n_in,
                              void* d_out, int out_size)
{
    const float* x  = (const float*)d_in[0];
    const float* W1 = (const float*)d_in[1];
    const float* b1 = (const float*)d_in[2];
    const float* W2 = (const float*)d_in[3];
    const float* b2 = (const float*)d_in[4];
    const float* W3 = (const float*)d_in[5];
    const float* b3 = (const float*)d_in[6];
    const float* W4 = (const float*)d_in[7];
    const float* b4 = (const float*)d_in[8];
    float* out = (float*)d_out;

    const int N = in_sizes[0] / 3;           // 262144
    const int smem_bytes = 2 * 4 * BUFQ * (int)sizeof(float);  // 128 KB

    cudaFuncSetAttribute(pinn_fused_kernel,
                         cudaFuncAttributeMaxDynamicSharedMemorySize, smem_bytes);

    pinn_fused_kernel<<<N / PTS, TPB, smem_bytes>>>(
        x, W1, b1, W2, b2, W3, b3, W4, b4, out);
}